// round 15
// baseline (speedup 1.0000x reference)
#include <cuda_runtime.h>
#include <cstdint>

#define Dd 128
#define NMAX 50000
#define EMAX 1000000
#define PADW 136   // W smem row stride (words); conflict-free per half-warp phase

// Scratch (static device globals -- no allocation allowed)
__device__ float g_u[NMAX * Dd];
__device__ float g_h[NMAX * Dd];
__device__ float g_dinv[NMAX];
__device__ float g_wt[4][Dd * Dd];   // transposed + tf32 + k-permuted weights [N][K']
__device__ int   g_cnt[NMAX];
__device__ int   g_deg[NMAX];
__device__ int   g_offs[NMAX];
__device__ int   g_cur[NMAX];
__device__ int   g_csr[EMAX];
__device__ int   g_bsum[256];

__device__ __forceinline__ uint32_t f2tf32(float v) {
    uint32_t r;
    asm("cvt.rna.tf32.f32 %0, %1;" : "=r"(r) : "f"(v));
    return r;
}

__device__ __forceinline__ void mma_tf32(float c[4], uint32_t a0, uint32_t a1,
                                         uint32_t a2, uint32_t a3,
                                         uint32_t b0, uint32_t b1) {
    asm volatile(
        "mma.sync.aligned.m16n8k8.row.col.f32.tf32.tf32.f32 "
        "{%0,%1,%2,%3}, {%4,%5,%6,%7}, {%8,%9}, {%0,%1,%2,%3};"
        : "+f"(c[0]), "+f"(c[1]), "+f"(c[2]), "+f"(c[3])
        : "r"(a0), "r"(a1), "r"(a2), "r"(a3), "r"(b0), "r"(b1));
}

__device__ __forceinline__ int warp_iscan(int v, int lane) {
#pragma unroll
    for (int d = 1; d < 32; d <<= 1) {
        int t = __shfl_up_sync(0xffffffff, v, d);
        if (lane >= d) v += t;
    }
    return v;
}

__device__ __forceinline__ float4 ldg4z(const float* p, bool v) {
    if (v) return __ldg((const float4*)p);
    return make_float4(0.f, 0.f, 0.f, 0.f);
}

// ---------------------------------------------------------------------------
// Persistent tf32 mma.sync GEMM, warp tile 32 rows x 64 cols:
// each uint2 B fragment is reused by TWO HMMAs (m-frags rows r/r+8, r+16/r+24)
// -> B LDS per warp per supergroup halves (16 vs 32).
// Warps 0-3 cover col half 0, warps 4-7 col half 1; block tile 128x128.
// A: LDG.128 per row-stream per supergroup (4 streams), prefetch depth 1.
//  mode 0: aux=dinv -> C = val*dinv[row]
//  mode 1: aux=bias -> C = relu(val + bias)
//  nheads==2: block parity selects (Wt1,aux1,C1)
// ---------------------------------------------------------------------------
__global__ void __launch_bounds__(256, 2) k_mma_gemm(
    const float* __restrict__ A,
    const float* __restrict__ Wt0, const float* __restrict__ aux0, float* __restrict__ C0,
    const float* Wt1, const float* aux1, float* C1,
    int n, int mode, int nheads)
{
    extern __shared__ float sm[];
    uint32_t* Wsu = (uint32_t*)sm;   // [128][PADW]

    int tid  = threadIdx.x;
    int wid  = tid >> 5;
    int lane = tid & 31;

    int ntiles = (n + 127) >> 7;
    int tile0, tstep;
    const float* Wt; const float* aux; float* C;
    if (nheads == 2) {
        int head = blockIdx.x & 1;
        tile0 = blockIdx.x >> 1;
        tstep = gridDim.x >> 1;
        Wt = head ? Wt1 : Wt0; aux = head ? aux1 : aux0; C = head ? C1 : C0;
    } else {
        tile0 = blockIdx.x;
        tstep = gridDim.x;
        Wt = Wt0; aux = aux0; C = C0;
    }

    const uint4* Wt4 = (const uint4*)Wt;
#pragma unroll
    for (int i = 0; i < 16; i++) {
        int f = tid + i * 256;
        int r = f >> 5, j = (f & 31) << 2;
        *(uint4*)(Wsu + r * PADW + j) = Wt4[f];
    }
    __syncthreads();

    int kq   = lane & 3;
    int bn0  = lane >> 2;
    int wid2 = wid & 3;          // row group
    int colh = (wid >> 2) * 64;  // column half base

    for (int tile = tile0; tile < ntiles; tile += tstep) {
        int row0 = tile << 7;
        int rbase = row0 + wid2 * 32 + (lane >> 2);
        int rr[4];
        bool vv[4];
        const float* ap[4];
#pragma unroll
        for (int m = 0; m < 4; m++) {
            rr[m] = rbase + 8 * m;
            vv[m] = rr[m] < n;
            ap[m] = A + (size_t)rr[m] * 128 + (kq << 2);
        }

        float c[8][2][4];
#pragma unroll
        for (int nt = 0; nt < 8; nt++)
#pragma unroll
            for (int f = 0; f < 2; f++)
#pragma unroll
                for (int q = 0; q < 4; q++) c[nt][f][q] = 0.0f;

        float4 fA[4];
#pragma unroll
        for (int m = 0; m < 4; m++) fA[m] = ldg4z(ap[m], vv[m]);

#pragma unroll
        for (int G = 0; G < 8; G++) {
            float4 nA[4];
            if (G < 7) {
#pragma unroll
                for (int m = 0; m < 4; m++) nA[m] = ldg4z(ap[m] + (G + 1) * 16, vv[m]);
            }
            // frag f=0: rows rbase, rbase+8 ; f=1: rows rbase+16, rbase+24
            uint32_t ax[2][4];
#pragma unroll
            for (int f = 0; f < 2; f++) {
                ax[f][0] = f2tf32(fA[2 * f].x);     // MMA1 a0
                ax[f][1] = f2tf32(fA[2 * f + 1].x); // MMA1 a1
                ax[f][2] = f2tf32(fA[2 * f].y);     // MMA1 a2
                ax[f][3] = f2tf32(fA[2 * f + 1].y); // MMA1 a3
            }
            uint32_t ay[2][4];
#pragma unroll
            for (int f = 0; f < 2; f++) {
                ay[f][0] = f2tf32(fA[2 * f].z);
                ay[f][1] = f2tf32(fA[2 * f + 1].z);
                ay[f][2] = f2tf32(fA[2 * f].w);
                ay[f][3] = f2tf32(fA[2 * f + 1].w);
            }
            int gbase = G * 16 + (kq << 1);
#pragma unroll
            for (int nt = 0; nt < 8; nt++) {
                const uint32_t* wr = Wsu + (colh + nt * 8 + bn0) * PADW + gbase;
                uint2 b0 = *(const uint2*)wr;
                uint2 b1 = *(const uint2*)(wr + 8);
#pragma unroll
                for (int f = 0; f < 2; f++) {
                    mma_tf32(c[nt][f], ax[f][0], ax[f][1], ax[f][2], ax[f][3], b0.x, b0.y);
                    mma_tf32(c[nt][f], ay[f][0], ay[f][1], ay[f][2], ay[f][3], b1.x, b1.y);
                }
            }
            if (G < 7) {
#pragma unroll
                for (int m = 0; m < 4; m++) fA[m] = nA[m];
            }
        }

        int cc = colh + kq * 2;
        if (mode == 0) {
            float dd[4];
#pragma unroll
            for (int m = 0; m < 4; m++) dd[m] = vv[m] ? aux[rr[m]] : 0.0f;
#pragma unroll
            for (int nt = 0; nt < 8; nt++) {
                int col = nt * 8 + cc;
#pragma unroll
                for (int f = 0; f < 2; f++) {
                    if (vv[2 * f])
                        *(float2*)(C + (size_t)rr[2 * f] * 128 + col) =
                            make_float2(c[nt][f][0] * dd[2 * f], c[nt][f][1] * dd[2 * f]);
                    if (vv[2 * f + 1])
                        *(float2*)(C + (size_t)rr[2 * f + 1] * 128 + col) =
                            make_float2(c[nt][f][2] * dd[2 * f + 1], c[nt][f][3] * dd[2 * f + 1]);
                }
            }
        } else {
#pragma unroll
            for (int nt = 0; nt < 8; nt++) {
                int col = nt * 8 + cc;
                float2 bb = *(const float2*)(aux + col);
#pragma unroll
                for (int f = 0; f < 2; f++) {
                    if (vv[2 * f])
                        *(float2*)(C + (size_t)rr[2 * f] * 128 + col) =
                            make_float2(fmaxf(c[nt][f][0] + bb.x, 0.f),
                                        fmaxf(c[nt][f][1] + bb.y, 0.f));
                    if (vv[2 * f + 1])
                        *(float2*)(C + (size_t)rr[2 * f + 1] * 128 + col) =
                            make_float2(fmaxf(c[nt][f][2] + bb.x, 0.f),
                                        fmaxf(c[nt][f][3] + bb.y, 0.f));
                }
            }
        }
    }
}

// ---------------------------------------------------------------------------
// prep: Wt[w][n][perm(k)] = tf32(W[k][n]); zero cnt[]
// perm within 16-group: kq=(k>>2)&3, s=(k>>1)&1, t=k&1 -> (s<<3)|(kq<<1)|t
// ---------------------------------------------------------------------------
__global__ void k_prep(const float* __restrict__ W0, const float* __restrict__ W1,
                       const float* __restrict__ W2, const float* __restrict__ W3,
                       float* __restrict__ Wt, int* __restrict__ cnt, int n) {
    int i = blockIdx.x * blockDim.x + threadIdx.x;
    if (i < 4 * Dd * Dd) {
        int w = i >> 14, r = i & (Dd * Dd - 1);
        const float* W = (w == 0) ? W0 : (w == 1) ? W1 : (w == 2) ? W2 : W3;
        int k = r >> 7, nn = r & 127;
        int kp = (k & ~15) | (((k >> 1) & 1) << 3) | (((k >> 2) & 3) << 1) | (k & 1);
        ((uint32_t*)Wt)[w * Dd * Dd + nn * Dd + kp] = f2tf32(W[k * Dd + nn]);
    }
    if (i < n) cnt[i] = 0;
}

// ---------------------------------------------------------------------------
// CSR build (R10-proven chain)
// ---------------------------------------------------------------------------
__global__ void k_hist(const int* __restrict__ dst, int* cnt, int E, int n) {
    int e = blockIdx.x * blockDim.x + threadIdx.x;
    if (e < E) {
        int d = dst[e];
        if ((unsigned)d < (unsigned)n) atomicAdd(&cnt[d], 1);
    }
}

__global__ void k_scan1(const int* __restrict__ cnt, int* offs, int* bsum, int n) {
    __shared__ int ws[8];
    int tid = threadIdx.x, lane = tid & 31, wid = tid >> 5;
    int i = blockIdx.x * 256 + tid;
    int v = (i < n) ? cnt[i] : 0;
    int s = warp_iscan(v, lane);
    if (lane == 31) ws[wid] = s;
    __syncthreads();
    if (wid == 0) {
        int t = (lane < 8) ? ws[lane] : 0;
        t = warp_iscan(t, lane);
        if (lane < 8) ws[lane] = t;
    }
    __syncthreads();
    int base = wid ? ws[wid - 1] : 0;
    if (i < n) offs[i] = base + s - v;
    if (tid == 255) bsum[blockIdx.x] = base + s;
}

// scan2+scan3 merged: each block reduces bsum[0..blockIdx.x) itself
__global__ void k_scan23(int* offs, const int* __restrict__ bsum,
                         const int* __restrict__ cnt, int* cur, int* deg,
                         float* dinv, int n) {
    __shared__ int ws[8];
    int tid = threadIdx.x, lane = tid & 31, wid = tid >> 5;
    int v = (tid < (int)blockIdx.x) ? bsum[tid] : 0;   // gridDim <= 256
#pragma unroll
    for (int d = 16; d > 0; d >>= 1) v += __shfl_down_sync(0xffffffff, v, d);
    if (lane == 0) ws[wid] = v;
    __syncthreads();
    if (tid == 0) {
        int t = 0;
#pragma unroll
        for (int q = 0; q < 8; q++) t += ws[q];
        ws[0] = t;
    }
    __syncthreads();
    int pre = ws[0];
    int i = blockIdx.x * 256 + tid;
    if (i < n) {
        offs[i] += pre;
        cur[i] = 0;
        int dv = cnt[i];
        deg[i] = dv;
        dinv[i] = rsqrtf((float)dv + 1.0f);  // +1 self loop
    }
}

__global__ void k_fill(const int* __restrict__ src, const int* __restrict__ dst,
                       const int* __restrict__ offs, int* cur, int* csr, int E, int n) {
    int e = blockIdx.x * blockDim.x + threadIdx.x;
    if (e < E) {
        int d = dst[e];
        int s = src[e];
        if ((unsigned)d < (unsigned)n && (unsigned)s < (unsigned)n) {
            int p = offs[d] + atomicAdd(&cur[d], 1);
            csr[p] = s;
        }
    }
}

// ---------------------------------------------------------------------------
// CSR gather-reduce + fused epilogue: out = relu?((u[i] + sum u[src])*dinv + b)
// ---------------------------------------------------------------------------
__global__ void __launch_bounds__(256) k_gather(
    const float* __restrict__ u, const int* __restrict__ csr,
    const int* __restrict__ offs, const int* __restrict__ deg,
    const float* __restrict__ dinv, const float* __restrict__ b,
    float* __restrict__ out, int n, int relu)
{
    int node = (blockIdx.x * 256 + threadIdx.x) >> 5;
    if (node >= n) return;
    int lane = threadIdx.x & 31;
    int j4 = lane << 2;

    float4 acc = *(const float4*)(u + (size_t)node * 128 + j4);
    int beg = offs[node];
    int m = deg[node];

    for (int base = 0; base < m; base += 32) {
        int rem = min(32, m - base);
        int s = (base + lane < m) ? __ldg(&csr[beg + base + lane]) : 0;
#pragma unroll 4
        for (int j = 0; j < rem; j++) {
            int sj = __shfl_sync(0xffffffff, s, j);
            float4 v = *(const float4*)(u + (size_t)sj * 128 + j4);
            acc.x += v.x; acc.y += v.y; acc.z += v.z; acc.w += v.w;
        }
    }

    float di = dinv[node];
    float4 bb = *(const float4*)(b + j4);
    acc.x = acc.x * di + bb.x;
    acc.y = acc.y * di + bb.y;
    acc.z = acc.z * di + bb.z;
    acc.w = acc.w * di + bb.w;
    if (relu) {
        acc.x = fmaxf(acc.x, 0.f); acc.y = fmaxf(acc.y, 0.f);
        acc.z = fmaxf(acc.z, 0.f); acc.w = fmaxf(acc.w, 0.f);
    }
    *(float4*)(out + (size_t)node * 128 + j4) = acc;
}

// ---------------------------------------------------------------------------
extern "C" void kernel_launch(void* const* d_in, const int* in_sizes, int n_in,
                              void* d_out, int out_size)
{
    const float* x  = (const float*)d_in[0];
    const int*   ei = (const int*)d_in[1];     // int32 (JAX x64 disabled)
    const float* W0 = (const float*)d_in[2];
    const float* b0 = (const float*)d_in[3];
    const float* W1 = (const float*)d_in[4];
    const float* b1 = (const float*)d_in[5];
    const float* Wv = (const float*)d_in[6];
    const float* bv = (const float*)d_in[7];
    const float* Wt = (const float*)d_in[8];
    const float* bt = (const float*)d_in[9];

    int n = in_sizes[0] / Dd;
    int E = in_sizes[1] / 2;
    if (E > EMAX) E = EMAX;
    const int* srcp = ei;
    const int* dstp = ei + E;

    float* out_h = (float*)d_out;
    float* out_v = out_h + (size_t)n * Dd;
    float* out_t = out_v + (size_t)n * Dd;

    float *u, *h, *dinv, *wt;
    int *cnt, *deg, *offs, *cur, *csr, *bsum;
    cudaGetSymbolAddress((void**)&u,    g_u);
    cudaGetSymbolAddress((void**)&h,    g_h);
    cudaGetSymbolAddress((void**)&dinv, g_dinv);
    cudaGetSymbolAddress((void**)&wt,   g_wt);
    cudaGetSymbolAddress((void**)&cnt,  g_cnt);
    cudaGetSymbolAddress((void**)&deg,  g_deg);
    cudaGetSymbolAddress((void**)&offs, g_offs);
    cudaGetSymbolAddress((void**)&cur,  g_cur);
    cudaGetSymbolAddress((void**)&csr,  g_csr);
    cudaGetSymbolAddress((void**)&bsum, g_bsum);

    float* wt0 = wt;
    float* wt1 = wt + Dd * Dd;
    float* wtv = wt + 2 * Dd * Dd;
    float* wtt = wt + 3 * Dd * Dd;

    const int SMEM_GEMM = 128 * PADW * 4;   // 69632 bytes (W only); 2 blocks/SM

    static bool attr_set = false;
    if (!attr_set) {
        cudaFuncSetAttribute(k_mma_gemm, cudaFuncAttributeMaxDynamicSharedMemorySize, SMEM_GEMM);
        attr_set = true;
    }

    int nb256 = (n + 255) / 256;
    int eb256 = (E + 255) / 256;
    int gathB = (n * 32 + 255) / 256;
    int prepB = (4 * Dd * Dd + 255) / 256;
    const int GEMMB = 296;   // persistent: 2 blocks/SM on 148 SMs

    // prep + CSR build (R10 chain)
    k_prep<<<prepB, 256>>>(W0, W1, Wv, Wt, wt, cnt, n);
    k_hist<<<eb256, 256>>>(dstp, cnt, E, n);
    k_scan1<<<nb256, 256>>>(cnt, offs, bsum, n);
    k_scan23<<<nb256, 256>>>(offs, bsum, cnt, cur, deg, dinv, n);
    k_fill<<<eb256, 256>>>(srcp, dstp, offs, cur, csr, E, n);

    // layer 0
    k_mma_gemm<<<GEMMB, 256, SMEM_GEMM>>>(x, wt0, dinv, u,
                                          nullptr, nullptr, nullptr, n, 0, 1);
    k_gather<<<gathB, 256>>>(u, csr, offs, deg, dinv, b0, h, n, 1);

    // layer 1 (no relu), writes into d_out
    k_mma_gemm<<<GEMMB, 256, SMEM_GEMM>>>(h, wt1, dinv, u,
                                          nullptr, nullptr, nullptr, n, 0, 1);
    k_gather<<<gathB, 256>>>(u, csr, offs, deg, dinv, b1, out_h, n, 0);

    // both heads, one persistent launch (block parity selects head)
    k_mma_gemm<<<GEMMB, 256, SMEM_GEMM>>>(out_h, wtv, bv, out_v,
                                          wtt, bt, out_t, n, 1, 2);
}

// round 16
// speedup vs baseline: 1.0690x; 1.0690x over previous
#include <cuda_runtime.h>
#include <cstdint>

#define Dd 128
#define NMAX 50000
#define EMAX 1000000
#define PADW 136   // W smem row stride (words); conflict-free per half-warp phase

// Scratch (static device globals -- no allocation allowed)
__device__ float g_u[NMAX * Dd];
__device__ float g_h[NMAX * Dd];
__device__ float g_dinv[NMAX];
__device__ float g_wt[4][Dd * Dd];   // transposed + tf32 + k-permuted weights [N][K']
__device__ int   g_cnt[NMAX];
__device__ int   g_deg[NMAX];
__device__ int   g_offs[NMAX];
__device__ int   g_cur[NMAX];
__device__ int   g_csr[EMAX];
__device__ int   g_bsum[256];
__device__ int   g_tctr[4];          // dynamic tile counters (zeroed by k_prep each call)

__device__ __forceinline__ uint32_t f2tf32(float v) {
    uint32_t r;
    asm("cvt.rna.tf32.f32 %0, %1;" : "=r"(r) : "f"(v));
    return r;
}

__device__ __forceinline__ void mma_tf32(float c[4], uint32_t a0, uint32_t a1,
                                         uint32_t a2, uint32_t a3,
                                         uint32_t b0, uint32_t b1) {
    asm volatile(
        "mma.sync.aligned.m16n8k8.row.col.f32.tf32.tf32.f32 "
        "{%0,%1,%2,%3}, {%4,%5,%6,%7}, {%8,%9}, {%0,%1,%2,%3};"
        : "+f"(c[0]), "+f"(c[1]), "+f"(c[2]), "+f"(c[3])
        : "r"(a0), "r"(a1), "r"(a2), "r"(a3), "r"(b0), "r"(b1));
}

__device__ __forceinline__ int warp_iscan(int v, int lane) {
#pragma unroll
    for (int d = 1; d < 32; d <<= 1) {
        int t = __shfl_up_sync(0xffffffff, v, d);
        if (lane >= d) v += t;
    }
    return v;
}

__device__ __forceinline__ float4 ldg4z(const float* p, bool v) {
    if (v) return __ldg((const float4*)p);
    return make_float4(0.f, 0.f, 0.f, 0.f);
}

// ---------------------------------------------------------------------------
// Persistent tf32 mma.sync GEMM (R10 inner loop: permuted W, uint2 B-frags,
// A LDG.128 prefetch depth 1) with DYNAMIC tile stealing via g_tctr[cidx]:
// balances tiles across SMs (static stride left some SMs with 4 tiles vs 2.64 avg).
//  mode 0: aux=dinv -> C = val*dinv[row]
//  mode 1: aux=bias -> C = relu(val + bias)
//  nheads==2: block parity selects head (Wt1,aux1,C1) and counter cidx+head
// ---------------------------------------------------------------------------
__global__ void __launch_bounds__(256, 2) k_mma_gemm(
    const float* __restrict__ A,
    const float* __restrict__ Wt0, const float* __restrict__ aux0, float* __restrict__ C0,
    const float* Wt1, const float* aux1, float* C1,
    int n, int mode, int nheads, int cidx)
{
    extern __shared__ float sm[];
    uint32_t* Wsu = (uint32_t*)sm;   // [128][PADW]
    __shared__ int stile;

    int tid  = threadIdx.x;
    int lane = tid & 31;
    int wid  = tid >> 5;

    int ntiles = (n + 127) >> 7;
    const float* Wt; const float* aux; float* C;
    if (nheads == 2) {
        int head = blockIdx.x & 1;
        cidx += head;
        Wt = head ? Wt1 : Wt0; aux = head ? aux1 : aux0; C = head ? C1 : C0;
    } else {
        Wt = Wt0; aux = aux0; C = C0;
    }

    const uint4* Wt4 = (const uint4*)Wt;
#pragma unroll
    for (int i = 0; i < 16; i++) {
        int f = tid + i * 256;
        int r = f >> 5, j = (f & 31) << 2;
        *(uint4*)(Wsu + r * PADW + j) = Wt4[f];
    }
    __syncthreads();

    int kq  = lane & 3;
    int bn0 = lane >> 2;

    for (;;) {
        if (tid == 0) stile = atomicAdd(&g_tctr[cidx], 1);
        __syncthreads();
        int tile = stile;
        __syncthreads();
        if (tile >= ntiles) break;

        int row0 = tile << 7;
        int r0 = row0 + wid * 16 + (lane >> 2);
        int r1 = r0 + 8;
        bool v0 = r0 < n, v1 = r1 < n;
        const float* a0p = A + (size_t)r0 * 128 + (kq << 2);
        const float* a1p = a0p + 8 * 128;

        float c[16][4];
#pragma unroll
        for (int nt = 0; nt < 16; nt++)
#pragma unroll
            for (int q = 0; q < 4; q++) c[nt][q] = 0.0f;

        float4 fA = ldg4z(a0p, v0);
        float4 fB = ldg4z(a1p, v1);

#pragma unroll
        for (int G = 0; G < 8; G++) {
            float4 nA, nB;
            if (G < 7) {
                nA = ldg4z(a0p + (G + 1) * 16, v0);
                nB = ldg4z(a1p + (G + 1) * 16, v1);
            }
            uint32_t a00 = f2tf32(fA.x), a10 = f2tf32(fB.x);
            uint32_t a20 = f2tf32(fA.y), a30 = f2tf32(fB.y);
            uint32_t a01 = f2tf32(fA.z), a11 = f2tf32(fB.z);
            uint32_t a21 = f2tf32(fA.w), a31 = f2tf32(fB.w);
            int gbase = G * 16 + (kq << 1);
#pragma unroll
            for (int nt = 0; nt < 16; nt++) {
                const uint32_t* wr = Wsu + (nt * 8 + bn0) * PADW + gbase;
                uint2 b0 = *(const uint2*)wr;
                uint2 b1 = *(const uint2*)(wr + 8);
                mma_tf32(c[nt], a00, a10, a20, a30, b0.x, b0.y);
                mma_tf32(c[nt], a01, a11, a21, a31, b1.x, b1.y);
            }
            fA = nA; fB = nB;
        }

        int cc = kq * 2;
        if (mode == 0) {
            float d0 = v0 ? aux[r0] : 0.0f;
            float d1 = v1 ? aux[r1] : 0.0f;
#pragma unroll
            for (int nt = 0; nt < 16; nt++) {
                int col = nt * 8 + cc;
                if (v0)
                    *(float2*)(C + (size_t)r0 * 128 + col) =
                        make_float2(c[nt][0] * d0, c[nt][1] * d0);
                if (v1)
                    *(float2*)(C + (size_t)r1 * 128 + col) =
                        make_float2(c[nt][2] * d1, c[nt][3] * d1);
            }
        } else {
#pragma unroll
            for (int nt = 0; nt < 16; nt++) {
                int col = nt * 8 + cc;
                float2 bb = *(const float2*)(aux + col);
                if (v0)
                    *(float2*)(C + (size_t)r0 * 128 + col) =
                        make_float2(fmaxf(c[nt][0] + bb.x, 0.f), fmaxf(c[nt][1] + bb.y, 0.f));
                if (v1)
                    *(float2*)(C + (size_t)r1 * 128 + col) =
                        make_float2(fmaxf(c[nt][2] + bb.x, 0.f), fmaxf(c[nt][3] + bb.y, 0.f));
            }
        }
    }
}

// ---------------------------------------------------------------------------
// prep: Wt[w][n][perm(k)] = tf32(W[k][n]); zero cnt[] and tile counters
// perm within 16-group: kq=(k>>2)&3, s=(k>>1)&1, t=k&1 -> (s<<3)|(kq<<1)|t
// ---------------------------------------------------------------------------
__global__ void k_prep(const float* __restrict__ W0, const float* __restrict__ W1,
                       const float* __restrict__ W2, const float* __restrict__ W3,
                       float* __restrict__ Wt, int* __restrict__ cnt, int n) {
    int i = blockIdx.x * blockDim.x + threadIdx.x;
    if (i < 4) g_tctr[i] = 0;
    if (i < 4 * Dd * Dd) {
        int w = i >> 14, r = i & (Dd * Dd - 1);
        const float* W = (w == 0) ? W0 : (w == 1) ? W1 : (w == 2) ? W2 : W3;
        int k = r >> 7, nn = r & 127;
        int kp = (k & ~15) | (((k >> 1) & 1) << 3) | (((k >> 2) & 3) << 1) | (k & 1);
        ((uint32_t*)Wt)[w * Dd * Dd + nn * Dd + kp] = f2tf32(W[k * Dd + nn]);
    }
    if (i < n) cnt[i] = 0;
}

// ---------------------------------------------------------------------------
// CSR build (R10-proven chain)
// ---------------------------------------------------------------------------
__global__ void k_hist(const int* __restrict__ dst, int* cnt, int E, int n) {
    int e = blockIdx.x * blockDim.x + threadIdx.x;
    if (e < E) {
        int d = dst[e];
        if ((unsigned)d < (unsigned)n) atomicAdd(&cnt[d], 1);
    }
}

__global__ void k_scan1(const int* __restrict__ cnt, int* offs, int* bsum, int n) {
    __shared__ int ws[8];
    int tid = threadIdx.x, lane = tid & 31, wid = tid >> 5;
    int i = blockIdx.x * 256 + tid;
    int v = (i < n) ? cnt[i] : 0;
    int s = warp_iscan(v, lane);
    if (lane == 31) ws[wid] = s;
    __syncthreads();
    if (wid == 0) {
        int t = (lane < 8) ? ws[lane] : 0;
        t = warp_iscan(t, lane);
        if (lane < 8) ws[lane] = t;
    }
    __syncthreads();
    int base = wid ? ws[wid - 1] : 0;
    if (i < n) offs[i] = base + s - v;
    if (tid == 255) bsum[blockIdx.x] = base + s;
}

// scan2+scan3 merged: each block reduces bsum[0..blockIdx.x) itself
__global__ void k_scan23(int* offs, const int* __restrict__ bsum,
                         const int* __restrict__ cnt, int* cur, int* deg,
                         float* dinv, int n) {
    __shared__ int ws[8];
    int tid = threadIdx.x, lane = tid & 31, wid = tid >> 5;
    int v = (tid < (int)blockIdx.x) ? bsum[tid] : 0;   // gridDim <= 256
#pragma unroll
    for (int d = 16; d > 0; d >>= 1) v += __shfl_down_sync(0xffffffff, v, d);
    if (lane == 0) ws[wid] = v;
    __syncthreads();
    if (tid == 0) {
        int t = 0;
#pragma unroll
        for (int q = 0; q < 8; q++) t += ws[q];
        ws[0] = t;
    }
    __syncthreads();
    int pre = ws[0];
    int i = blockIdx.x * 256 + tid;
    if (i < n) {
        offs[i] += pre;
        cur[i] = 0;
        int dv = cnt[i];
        deg[i] = dv;
        dinv[i] = rsqrtf((float)dv + 1.0f);  // +1 self loop
    }
}

__global__ void k_fill(const int* __restrict__ src, const int* __restrict__ dst,
                       const int* __restrict__ offs, int* cur, int* csr, int E, int n) {
    int e = blockIdx.x * blockDim.x + threadIdx.x;
    if (e < E) {
        int d = dst[e];
        int s = src[e];
        if ((unsigned)d < (unsigned)n && (unsigned)s < (unsigned)n) {
            int p = offs[d] + atomicAdd(&cur[d], 1);
            csr[p] = s;
        }
    }
}

// ---------------------------------------------------------------------------
// CSR gather-reduce + fused epilogue: out = relu?((u[i] + sum u[src])*dinv + b)
// ---------------------------------------------------------------------------
__global__ void __launch_bounds__(256) k_gather(
    const float* __restrict__ u, const int* __restrict__ csr,
    const int* __restrict__ offs, const int* __restrict__ deg,
    const float* __restrict__ dinv, const float* __restrict__ b,
    float* __restrict__ out, int n, int relu)
{
    int node = (blockIdx.x * 256 + threadIdx.x) >> 5;
    if (node >= n) return;
    int lane = threadIdx.x & 31;
    int j4 = lane << 2;

    float4 acc = *(const float4*)(u + (size_t)node * 128 + j4);
    int beg = offs[node];
    int m = deg[node];

    for (int base = 0; base < m; base += 32) {
        int rem = min(32, m - base);
        int s = (base + lane < m) ? __ldg(&csr[beg + base + lane]) : 0;
#pragma unroll 4
        for (int j = 0; j < rem; j++) {
            int sj = __shfl_sync(0xffffffff, s, j);
            float4 v = *(const float4*)(u + (size_t)sj * 128 + j4);
            acc.x += v.x; acc.y += v.y; acc.z += v.z; acc.w += v.w;
        }
    }

    float di = dinv[node];
    float4 bb = *(const float4*)(b + j4);
    acc.x = acc.x * di + bb.x;
    acc.y = acc.y * di + bb.y;
    acc.z = acc.z * di + bb.z;
    acc.w = acc.w * di + bb.w;
    if (relu) {
        acc.x = fmaxf(acc.x, 0.f); acc.y = fmaxf(acc.y, 0.f);
        acc.z = fmaxf(acc.z, 0.f); acc.w = fmaxf(acc.w, 0.f);
    }
    *(float4*)(out + (size_t)node * 128 + j4) = acc;
}

// ---------------------------------------------------------------------------
extern "C" void kernel_launch(void* const* d_in, const int* in_sizes, int n_in,
                              void* d_out, int out_size)
{
    const float* x  = (const float*)d_in[0];
    const int*   ei = (const int*)d_in[1];     // int32 (JAX x64 disabled)
    const float* W0 = (const float*)d_in[2];
    const float* b0 = (const float*)d_in[3];
    const float* W1 = (const float*)d_in[4];
    const float* b1 = (const float*)d_in[5];
    const float* Wv = (const float*)d_in[6];
    const float* bv = (const float*)d_in[7];
    const float* Wt = (const float*)d_in[8];
    const float* bt = (const float*)d_in[9];

    int n = in_sizes[0] / Dd;
    int E = in_sizes[1] / 2;
    if (E > EMAX) E = EMAX;
    const int* srcp = ei;
    const int* dstp = ei + E;

    float* out_h = (float*)d_out;
    float* out_v = out_h + (size_t)n * Dd;
    float* out_t = out_v + (size_t)n * Dd;

    float *u, *h, *dinv, *wt;
    int *cnt, *deg, *offs, *cur, *csr, *bsum;
    cudaGetSymbolAddress((void**)&u,    g_u);
    cudaGetSymbolAddress((void**)&h,    g_h);
    cudaGetSymbolAddress((void**)&dinv, g_dinv);
    cudaGetSymbolAddress((void**)&wt,   g_wt);
    cudaGetSymbolAddress((void**)&cnt,  g_cnt);
    cudaGetSymbolAddress((void**)&deg,  g_deg);
    cudaGetSymbolAddress((void**)&offs, g_offs);
    cudaGetSymbolAddress((void**)&cur,  g_cur);
    cudaGetSymbolAddress((void**)&csr,  g_csr);
    cudaGetSymbolAddress((void**)&bsum, g_bsum);

    float* wt0 = wt;
    float* wt1 = wt + Dd * Dd;
    float* wtv = wt + 2 * Dd * Dd;
    float* wtt = wt + 3 * Dd * Dd;

    const int SMEM_GEMM = 128 * PADW * 4;   // 69632 bytes (W only); 2 blocks/SM

    static bool attr_set = false;
    if (!attr_set) {
        cudaFuncSetAttribute(k_mma_gemm, cudaFuncAttributeMaxDynamicSharedMemorySize, SMEM_GEMM);
        attr_set = true;
    }

    int nb256 = (n + 255) / 256;
    int eb256 = (E + 255) / 256;
    int gathB = (n * 32 + 255) / 256;
    int prepB = (4 * Dd * Dd + 255) / 256;
    const int GEMMB = 296;   // persistent: 2 blocks/SM on 148 SMs

    // prep + CSR build (R10 chain)
    k_prep<<<prepB, 256>>>(W0, W1, Wv, Wt, wt, cnt, n);
    k_hist<<<eb256, 256>>>(dstp, cnt, E, n);
    k_scan1<<<nb256, 256>>>(cnt, offs, bsum, n);
    k_scan23<<<nb256, 256>>>(offs, bsum, cnt, cur, deg, dinv, n);
    k_fill<<<eb256, 256>>>(srcp, dstp, offs, cur, csr, E, n);

    // layer 0 (dynamic tiles via counter 0)
    k_mma_gemm<<<GEMMB, 256, SMEM_GEMM>>>(x, wt0, dinv, u,
                                          nullptr, nullptr, nullptr, n, 0, 1, 0);
    k_gather<<<gathB, 256>>>(u, csr, offs, deg, dinv, b0, h, n, 1);

    // layer 1 (counter 1), writes into d_out
    k_mma_gemm<<<GEMMB, 256, SMEM_GEMM>>>(h, wt1, dinv, u,
                                          nullptr, nullptr, nullptr, n, 0, 1, 1);
    k_gather<<<gathB, 256>>>(u, csr, offs, deg, dinv, b1, out_h, n, 0);

    // both heads, one launch (parity selects head; counters 2 and 3)
    k_mma_gemm<<<GEMMB, 256, SMEM_GEMM>>>(out_h, wtv, bv, out_v,
                                          wtt, bt, out_t, n, 1, 2, 2);
}

// round 17
// speedup vs baseline: 1.0971x; 1.0263x over previous
#include <cuda_runtime.h>
#include <cstdint>

#define Dd 128
#define NMAX 50000
#define EMAX 1000000
#define PADW 136   // W smem row stride (words); conflict-free per half-warp phase

// Scratch (static device globals -- no allocation allowed)
__device__ float g_u[NMAX * Dd];
__device__ float g_h[NMAX * Dd];
__device__ float g_dinv[NMAX];
__device__ float g_wt[4][Dd * Dd];   // transposed + tf32 + k-permuted weights [N][K']
__device__ int   g_cnt[NMAX];        // zero-init at load; re-zeroed by k_scan23 each call
__device__ int   g_deg[NMAX];
__device__ int   g_offs[NMAX];
__device__ int   g_cur[NMAX];
__device__ int   g_csr[EMAX];
__device__ int   g_bsum[256];

__device__ __forceinline__ uint32_t f2tf32(float v) {
    uint32_t r;
    asm("cvt.rna.tf32.f32 %0, %1;" : "=r"(r) : "f"(v));
    return r;
}

__device__ __forceinline__ void mma_tf32(float c[4], uint32_t a0, uint32_t a1,
                                         uint32_t a2, uint32_t a3,
                                         uint32_t b0, uint32_t b1) {
    asm volatile(
        "mma.sync.aligned.m16n8k8.row.col.f32.tf32.tf32.f32 "
        "{%0,%1,%2,%3}, {%4,%5,%6,%7}, {%8,%9}, {%0,%1,%2,%3};"
        : "+f"(c[0]), "+f"(c[1]), "+f"(c[2]), "+f"(c[3])
        : "r"(a0), "r"(a1), "r"(a2), "r"(a3), "r"(b0), "r"(b1));
}

__device__ __forceinline__ int warp_iscan(int v, int lane) {
#pragma unroll
    for (int d = 1; d < 32; d <<= 1) {
        int t = __shfl_up_sync(0xffffffff, v, d);
        if (lane >= d) v += t;
    }
    return v;
}

__device__ __forceinline__ float4 ldg4z(const float* p, bool v) {
    if (v) return __ldg((const float4*)p);
    return make_float4(0.f, 0.f, 0.f, 0.f);
}

// ---------------------------------------------------------------------------
// Persistent tf32 mma.sync GEMM -- the R10 local optimum, verbatim:
// A via LDG.128 per 16-k supergroup (prefetch depth 1), W smem pre-permuted,
// uint2 B fragments, static tile stride.
//  mode 0: aux=dinv -> C = val*dinv[row]
//  mode 1: aux=bias -> C = relu(val + bias)
//  nheads==2: block parity selects (Wt1,aux1,C1)
// ---------------------------------------------------------------------------
__global__ void __launch_bounds__(256, 2) k_mma_gemm(
    const float* __restrict__ A,
    const float* __restrict__ Wt0, const float* __restrict__ aux0, float* __restrict__ C0,
    const float* Wt1, const float* aux1, float* C1,
    int n, int mode, int nheads)
{
    extern __shared__ float sm[];
    uint32_t* Wsu = (uint32_t*)sm;   // [128][PADW]

    int tid  = threadIdx.x;
    int wid  = tid >> 5;
    int lane = tid & 31;

    int ntiles = (n + 127) >> 7;
    int tile0, tstep;
    const float* Wt; const float* aux; float* C;
    if (nheads == 2) {
        int head = blockIdx.x & 1;
        tile0 = blockIdx.x >> 1;
        tstep = gridDim.x >> 1;
        Wt = head ? Wt1 : Wt0; aux = head ? aux1 : aux0; C = head ? C1 : C0;
    } else {
        tile0 = blockIdx.x;
        tstep = gridDim.x;
        Wt = Wt0; aux = aux0; C = C0;
    }

    const uint4* Wt4 = (const uint4*)Wt;
#pragma unroll
    for (int i = 0; i < 16; i++) {
        int f = tid + i * 256;
        int r = f >> 5, j = (f & 31) << 2;
        *(uint4*)(Wsu + r * PADW + j) = Wt4[f];
    }
    __syncthreads();

    int kq  = lane & 3;
    int bn0 = lane >> 2;

    for (int tile = tile0; tile < ntiles; tile += tstep) {
        int row0 = tile << 7;
        int r0 = row0 + wid * 16 + (lane >> 2);
        int r1 = r0 + 8;
        bool v0 = r0 < n, v1 = r1 < n;
        const float* a0p = A + (size_t)r0 * 128 + (kq << 2);
        const float* a1p = a0p + 8 * 128;

        float c[16][4];
#pragma unroll
        for (int nt = 0; nt < 16; nt++)
#pragma unroll
            for (int q = 0; q < 4; q++) c[nt][q] = 0.0f;

        float4 fA = ldg4z(a0p, v0);
        float4 fB = ldg4z(a1p, v1);

#pragma unroll
        for (int G = 0; G < 8; G++) {
            float4 nA, nB;
            if (G < 7) {
                nA = ldg4z(a0p + (G + 1) * 16, v0);
                nB = ldg4z(a1p + (G + 1) * 16, v1);
            }
            uint32_t a00 = f2tf32(fA.x), a10 = f2tf32(fB.x);
            uint32_t a20 = f2tf32(fA.y), a30 = f2tf32(fB.y);
            uint32_t a01 = f2tf32(fA.z), a11 = f2tf32(fB.z);
            uint32_t a21 = f2tf32(fA.w), a31 = f2tf32(fB.w);
            int gbase = G * 16 + (kq << 1);
#pragma unroll
            for (int nt = 0; nt < 16; nt++) {
                const uint32_t* wr = Wsu + (nt * 8 + bn0) * PADW + gbase;
                uint2 b0 = *(const uint2*)wr;
                uint2 b1 = *(const uint2*)(wr + 8);
                mma_tf32(c[nt], a00, a10, a20, a30, b0.x, b0.y);
                mma_tf32(c[nt], a01, a11, a21, a31, b1.x, b1.y);
            }
            fA = nA; fB = nB;
        }

        int cc = kq * 2;
        if (mode == 0) {
            float d0 = v0 ? aux[r0] : 0.0f;
            float d1 = v1 ? aux[r1] : 0.0f;
#pragma unroll
            for (int nt = 0; nt < 16; nt++) {
                int col = nt * 8 + cc;
                if (v0)
                    *(float2*)(C + (size_t)r0 * 128 + col) =
                        make_float2(c[nt][0] * d0, c[nt][1] * d0);
                if (v1)
                    *(float2*)(C + (size_t)r1 * 128 + col) =
                        make_float2(c[nt][2] * d1, c[nt][3] * d1);
            }
        } else {
#pragma unroll
            for (int nt = 0; nt < 16; nt++) {
                int col = nt * 8 + cc;
                float2 bb = *(const float2*)(aux + col);
                if (v0)
                    *(float2*)(C + (size_t)r0 * 128 + col) =
                        make_float2(fmaxf(c[nt][0] + bb.x, 0.f), fmaxf(c[nt][1] + bb.y, 0.f));
                if (v1)
                    *(float2*)(C + (size_t)r1 * 128 + col) =
                        make_float2(fmaxf(c[nt][2] + bb.x, 0.f), fmaxf(c[nt][3] + bb.y, 0.f));
            }
        }
    }
}

// ---------------------------------------------------------------------------
// fused weight-prep + degree histogram (cnt arrives zeroed: module init on
// call 1, re-zeroed by k_scan23 on every call).
// W perm within 16-group: kq=(k>>2)&3, s=(k>>1)&1, t=k&1 -> (s<<3)|(kq<<1)|t
// ---------------------------------------------------------------------------
__global__ void k_prep_hist(const float* __restrict__ W0, const float* __restrict__ W1,
                            const float* __restrict__ W2, const float* __restrict__ W3,
                            float* __restrict__ Wt,
                            const int* __restrict__ dst, int* __restrict__ cnt,
                            int E, int n) {
    int i = blockIdx.x * blockDim.x + threadIdx.x;
    if (i < 4 * Dd * Dd) {
        int w = i >> 14, r = i & (Dd * Dd - 1);
        const float* W = (w == 0) ? W0 : (w == 1) ? W1 : (w == 2) ? W2 : W3;
        int k = r >> 7, nn = r & 127;
        int kp = (k & ~15) | (((k >> 1) & 1) << 3) | (((k >> 2) & 3) << 1) | (k & 1);
        ((uint32_t*)Wt)[w * Dd * Dd + nn * Dd + kp] = f2tf32(W[k * Dd + nn]);
    }
    if (i < E) {
        int d = dst[i];
        if ((unsigned)d < (unsigned)n) atomicAdd(&cnt[d], 1);
    }
}

// ---------------------------------------------------------------------------
// CSR build: scan1 -> scan23 -> fill
// ---------------------------------------------------------------------------
__global__ void k_scan1(const int* __restrict__ cnt, int* offs, int* bsum, int n) {
    __shared__ int ws[8];
    int tid = threadIdx.x, lane = tid & 31, wid = tid >> 5;
    int i = blockIdx.x * 256 + tid;
    int v = (i < n) ? cnt[i] : 0;
    int s = warp_iscan(v, lane);
    if (lane == 31) ws[wid] = s;
    __syncthreads();
    if (wid == 0) {
        int t = (lane < 8) ? ws[lane] : 0;
        t = warp_iscan(t, lane);
        if (lane < 8) ws[lane] = t;
    }
    __syncthreads();
    int base = wid ? ws[wid - 1] : 0;
    if (i < n) offs[i] = base + s - v;
    if (tid == 255) bsum[blockIdx.x] = base + s;
}

// scan2+scan3 merged: each block reduces bsum[0..blockIdx.x) itself.
// Also re-zeroes cnt (after reading it into deg) for the next replay's hist.
__global__ void k_scan23(int* offs, const int* __restrict__ bsum,
                         int* __restrict__ cnt, int* cur, int* deg,
                         float* dinv, int n) {
    __shared__ int ws[8];
    int tid = threadIdx.x, lane = tid & 31, wid = tid >> 5;
    int v = (tid < (int)blockIdx.x) ? bsum[tid] : 0;   // gridDim <= 256
#pragma unroll
    for (int d = 16; d > 0; d >>= 1) v += __shfl_down_sync(0xffffffff, v, d);
    if (lane == 0) ws[wid] = v;
    __syncthreads();
    if (tid == 0) {
        int t = 0;
#pragma unroll
        for (int q = 0; q < 8; q++) t += ws[q];
        ws[0] = t;
    }
    __syncthreads();
    int pre = ws[0];
    int i = blockIdx.x * 256 + tid;
    if (i < n) {
        offs[i] += pre;
        cur[i] = 0;
        int dv = cnt[i];
        cnt[i] = 0;                  // recycle for next replay
        deg[i] = dv;
        dinv[i] = rsqrtf((float)dv + 1.0f);  // +1 self loop
    }
}

__global__ void k_fill(const int* __restrict__ src, const int* __restrict__ dst,
                       const int* __restrict__ offs, int* cur, int* csr, int E, int n) {
    int e = blockIdx.x * blockDim.x + threadIdx.x;
    if (e < E) {
        int d = dst[e];
        int s = src[e];
        if ((unsigned)d < (unsigned)n && (unsigned)s < (unsigned)n) {
            int p = offs[d] + atomicAdd(&cur[d], 1);
            csr[p] = s;
        }
    }
}

// ---------------------------------------------------------------------------
// CSR gather-reduce + fused epilogue: out = relu?((u[i] + sum u[src])*dinv + b)
// ---------------------------------------------------------------------------
__global__ void __launch_bounds__(256) k_gather(
    const float* __restrict__ u, const int* __restrict__ csr,
    const int* __restrict__ offs, const int* __restrict__ deg,
    const float* __restrict__ dinv, const float* __restrict__ b,
    float* __restrict__ out, int n, int relu)
{
    int node = (blockIdx.x * 256 + threadIdx.x) >> 5;
    if (node >= n) return;
    int lane = threadIdx.x & 31;
    int j4 = lane << 2;

    float4 acc = *(const float4*)(u + (size_t)node * 128 + j4);
    int beg = offs[node];
    int m = deg[node];

    for (int base = 0; base < m; base += 32) {
        int rem = min(32, m - base);
        int s = (base + lane < m) ? __ldg(&csr[beg + base + lane]) : 0;
#pragma unroll 4
        for (int j = 0; j < rem; j++) {
            int sj = __shfl_sync(0xffffffff, s, j);
            float4 v = *(const float4*)(u + (size_t)sj * 128 + j4);
            acc.x += v.x; acc.y += v.y; acc.z += v.z; acc.w += v.w;
        }
    }

    float di = dinv[node];
    float4 bb = *(const float4*)(b + j4);
    acc.x = acc.x * di + bb.x;
    acc.y = acc.y * di + bb.y;
    acc.z = acc.z * di + bb.z;
    acc.w = acc.w * di + bb.w;
    if (relu) {
        acc.x = fmaxf(acc.x, 0.f); acc.y = fmaxf(acc.y, 0.f);
        acc.z = fmaxf(acc.z, 0.f); acc.w = fmaxf(acc.w, 0.f);
    }
    *(float4*)(out + (size_t)node * 128 + j4) = acc;
}

// ---------------------------------------------------------------------------
extern "C" void kernel_launch(void* const* d_in, const int* in_sizes, int n_in,
                              void* d_out, int out_size)
{
    const float* x  = (const float*)d_in[0];
    const int*   ei = (const int*)d_in[1];     // int32 (JAX x64 disabled)
    const float* W0 = (const float*)d_in[2];
    const float* b0 = (const float*)d_in[3];
    const float* W1 = (const float*)d_in[4];
    const float* b1 = (const float*)d_in[5];
    const float* Wv = (const float*)d_in[6];
    const float* bv = (const float*)d_in[7];
    const float* Wt = (const float*)d_in[8];
    const float* bt = (const float*)d_in[9];

    int n = in_sizes[0] / Dd;
    int E = in_sizes[1] / 2;
    if (E > EMAX) E = EMAX;
    const int* srcp = ei;
    const int* dstp = ei + E;

    float* out_h = (float*)d_out;
    float* out_v = out_h + (size_t)n * Dd;
    float* out_t = out_v + (size_t)n * Dd;

    float *u, *h, *dinv, *wt;
    int *cnt, *deg, *offs, *cur, *csr, *bsum;
    cudaGetSymbolAddress((void**)&u,    g_u);
    cudaGetSymbolAddress((void**)&h,    g_h);
    cudaGetSymbolAddress((void**)&dinv, g_dinv);
    cudaGetSymbolAddress((void**)&wt,   g_wt);
    cudaGetSymbolAddress((void**)&cnt,  g_cnt);
    cudaGetSymbolAddress((void**)&deg,  g_deg);
    cudaGetSymbolAddress((void**)&offs, g_offs);
    cudaGetSymbolAddress((void**)&cur,  g_cur);
    cudaGetSymbolAddress((void**)&csr,  g_csr);
    cudaGetSymbolAddress((void**)&bsum, g_bsum);

    float* wt0 = wt;
    float* wt1 = wt + Dd * Dd;
    float* wtv = wt + 2 * Dd * Dd;
    float* wtt = wt + 3 * Dd * Dd;

    const int SMEM_GEMM = 128 * PADW * 4;   // 69632 bytes (W only); 2 blocks/SM

    static bool attr_set = false;
    if (!attr_set) {
        cudaFuncSetAttribute(k_mma_gemm, cudaFuncAttributeMaxDynamicSharedMemorySize, SMEM_GEMM);
        attr_set = true;
    }

    int nb256 = (n + 255) / 256;
    int eb256 = (E + 255) / 256;
    int gathB = (n * 32 + 255) / 256;
    const int GEMMB = 296;   // persistent: 2 blocks/SM on 148 SMs

    // CSR build: 4 launches (prep+hist fused; scan1; scan23; fill)
    k_prep_hist<<<eb256, 256>>>(W0, W1, Wv, Wt, wt, dstp, cnt, E, n);
    k_scan1<<<nb256, 256>>>(cnt, offs, bsum, n);
    k_scan23<<<nb256, 256>>>(offs, bsum, cnt, cur, deg, dinv, n);
    k_fill<<<eb256, 256>>>(srcp, dstp, offs, cur, csr, E, n);

    // layer 0
    k_mma_gemm<<<GEMMB, 256, SMEM_GEMM>>>(x, wt0, dinv, u,
                                          nullptr, nullptr, nullptr, n, 0, 1);
    k_gather<<<gathB, 256>>>(u, csr, offs, deg, dinv, b0, h, n, 1);

    // layer 1 (no relu), writes into d_out
    k_mma_gemm<<<GEMMB, 256, SMEM_GEMM>>>(h, wt1, dinv, u,
                                          nullptr, nullptr, nullptr, n, 0, 1);
    k_gather<<<gathB, 256>>>(u, csr, offs, deg, dinv, b1, out_h, n, 0);

    // both heads, one persistent launch (block parity selects head)
    k_mma_gemm<<<GEMMB, 256, SMEM_GEMM>>>(out_h, wtv, bv, out_v,
                                          wtt, bt, out_t, n, 1, 2);
}